// round 7
// baseline (speedup 1.0000x reference)
#include <cuda_runtime.h>
#include <cstdint>

#define T_STEPS 336
#define BATCH   4096
#define NFEAT   32
#define UN1     64
#define UN2     32
#define G1      256   // 4*UN1
#define G2      128   // 4*UN2
#define ROWS    32
#define THREADS 512
#define CTAS    (BATCH / ROWS)   // 128
#define RSTRIDE 128   // combined row: [x(32)|h1(64)|h2(32)]

// gate-quad interleaved weight rows: per k, [i,i',f,f',g,g',o,o'] per unit-pair,
// +4-float shift every 4 ups so LDS.128 is conflict-free per quarter-warp
#define WROW1 288     // 32 ups * 8 + 8 gaps * 4
#define WROW2 144     // 16 ups * 8 + 4 gaps * 4

// ---- shared memory layout (float offsets) ----
#define OFF_W1i 0                                     // 96 x WROW1
#define OFF_W2i (96 * WROW1)                          // 96 x WROW2
#define OFF_C   (OFF_W1i + 96 * WROW1 + 96 * WROW2)   // 2 x 32 x 128
#define SMEM_FLOATS (OFF_C + 2 * ROWS * RSTRIDE)      // 49664 -> 198656 bytes

typedef unsigned long long ull;

// ---------------- packed f32x2 helpers ----------------
__device__ __forceinline__ ull pack2(float a) {
    ull r; asm("mov.b64 %0, {%1, %1};" : "=l"(r) : "f"(a)); return r;
}
__device__ __forceinline__ ull pakf2(float x, float y) {
    ull r; asm("mov.b64 %0, {%1, %2};" : "=l"(r) : "f"(x), "f"(y)); return r;
}
__device__ __forceinline__ ull fma2(ull a, ull b, ull c) {
    ull d; asm("fma.rn.f32x2 %0, %1, %2, %3;" : "=l"(d) : "l"(a), "l"(b), "l"(c)); return d;
}
__device__ __forceinline__ ull add2(ull a, ull b) {
    ull d; asm("add.rn.f32x2 %0, %1, %2;" : "=l"(d) : "l"(a), "l"(b)); return d;
}
__device__ __forceinline__ float2 unpack2(ull v) {
    float2 r; asm("mov.b64 {%0, %1}, %2;" : "=f"(r.x), "=f"(r.y) : "l"(v)); return r;
}

// ---------------- activations (fast HW exp/rcp, ~1e-6 err) ----------------
__device__ __forceinline__ float sigm(float x) {
    float e = __expf(-x);
    return __fdividef(1.0f, 1.0f + e);
}
__device__ __forceinline__ float tanh_(float x) {
    float ax = fabsf(x);
    float e  = __expf(-2.0f * ax);
    float r  = __fdividef(1.0f - e, 1.0f + e);
    return copysignf(r, x);
}

// ---------------- cp.async helpers ----------------
__device__ __forceinline__ void cp16(uint32_t saddr, const float* g) {
    asm volatile("cp.async.cg.shared.global [%0], [%1], 16;" :: "r"(saddr), "l"(g));
}
__device__ __forceinline__ void cp_commit() { asm volatile("cp.async.commit_group;"); }
__device__ __forceinline__ void cp_wait0()  { asm volatile("cp.async.wait_group 0;" ::: "memory"); }

// COLS-column panel, R rows, gate-quad weights (2x LDS.128 per k),
// float4 input loads (broadcast within half-warp).
template <int R, int COLS, int WROW>
__device__ __forceinline__ void panelQ(ull (&acc)[R][4],
                                       const float* __restrict__ in,
                                       const float* __restrict__ wq) {
#pragma unroll 2
    for (int k = 0; k < COLS; k += 4) {
        float4 a[R];
#pragma unroll
        for (int r = 0; r < R; r++) a[r] = *(const float4*)(in + r * RSTRIDE + k);
        const float* w = wq + k * WROW;
        ulonglong2 wa, wb;
#pragma unroll
        for (int kk = 0; kk < 4; kk++) {
            wa = *(const ulonglong2*)(w + kk * WROW);
            wb = *(const ulonglong2*)(w + kk * WROW + 4);
#pragma unroll
            for (int r = 0; r < R; r++) {
                float av = (kk == 0) ? a[r].x : (kk == 1) ? a[r].y : (kk == 2) ? a[r].z : a[r].w;
                ull p = pack2(av);
                acc[r][0] = fma2(p, wa.x, acc[r][0]);
                acc[r][1] = fma2(p, wa.y, acc[r][1]);
                acc[r][2] = fma2(p, wb.x, acc[r][2]);
                acc[r][3] = fma2(p, wb.y, acc[r][3]);
            }
        }
    }
}

__global__ void __launch_bounds__(THREADS, 1)
lstm_fused_kernel(const float* __restrict__ x,
                  const float* __restrict__ W1, const float* __restrict__ U1w, const float* __restrict__ b1,
                  const float* __restrict__ W2, const float* __restrict__ U2w, const float* __restrict__ b2,
                  const float* __restrict__ Wv, const float* __restrict__ bv,
                  const float* __restrict__ Wo, const float* __restrict__ bo,
                  const float* __restrict__ Wd1, const float* __restrict__ bd1,
                  const float* __restrict__ Wd2, const float* __restrict__ bd2,
                  float* __restrict__ out) {
    extern __shared__ float sm[];
    const int tid = threadIdx.x;
    const int b0  = blockIdx.x * ROWS;

    // ---- stage weights into SMEM: gate-quad interleaved + bank-gap swizzle ----
    // L1 stacked [W1;U1]: 96 rows x 256 gate cols
    for (int idx = tid; idx < 96 * 256; idx += THREADS) {
        int k = idx >> 8, c = idx & 255;
        int gate = c >> 6, unit = c & 63;
        int u = unit >> 1, j = unit & 1;
        float v = (k < NFEAT) ? W1[k * G1 + c] : U1w[(k - NFEAT) * G1 + c];
        sm[OFF_W1i + k * WROW1 + u * 8 + (u >> 2) * 4 + gate * 2 + j] = v;
    }
    // L2 stacked [W2;U2]: 96 rows x 128 gate cols
    for (int idx = tid; idx < 96 * 128; idx += THREADS) {
        int k = idx >> 7, c = idx & 127;
        int gate = c >> 5, unit = c & 31;
        int u = unit >> 1, j = unit & 1;
        float v = (k < UN1) ? W2[k * G2 + c] : U2w[(k - UN1) * G2 + c];
        sm[OFF_W2i + k * WROW2 + u * 8 + (u >> 2) * 4 + gate * 2 + j] = v;
    }
    // zero both combined state buffers
    for (int i = tid; i < 2 * ROWS * RSTRIDE; i += THREADS) sm[OFF_C + i] = 0.0f;

    // ---- thread mapping: ALL warps do L1 (phase A), then ALL do L2 (phase B) ----
    const int wg = tid >> 5;           // 0..15
    const int l  = tid & 31;
    const int kh = l >> 4;             // K-half
    // Phase A (L1): 8 row groups x 32 unit pairs x 2 kh
    const int rg  = wg >> 1;                     // rows rg*4 .. +3
    const int up  = (l & 15) | ((wg & 1) << 4);  // unit pair 0..31
    // Phase B (L2): 16 row groups x 16 unit pairs x 2 kh
    const int rg2 = wg;                          // rows rg2*2 .. +1
    const int up2 = l & 15;                      // unit pair 0..15

    // bias -> registers (kh==0 half carries it; partner contributes 0)
    ull bq1[4], bq2[4];
#pragma unroll
    for (int g = 0; g < 4; g++) {
        float2 v1 = (kh == 0) ? *(const float2*)(b1 + g * UN1 + 2 * up)  : make_float2(0.f, 0.f);
        float2 v2 = (kh == 0) ? *(const float2*)(b2 + g * UN2 + 2 * up2) : make_float2(0.f, 0.f);
        bq1[g] = pakf2(v1.x, v1.y);
        bq2[g] = pakf2(v2.x, v2.y);
    }

    // per-thread cell state
    float c1[2][2];   // phase A: 2 rows x 2 units
    float c2[2];      // phase B: 1 row x 2 units
    c1[0][0] = c1[0][1] = c1[1][0] = c1[1][1] = 0.0f;
    c2[0] = c2[1] = 0.0f;

    // ---- x prefetch: threads 0-255 move one float4 per step ----
    const bool xmover = (tid < 256);
    const int xrow = tid >> 3;
    const int xq   = tid & 7;
    const float* xg = x + ((size_t)(b0 + xrow) * T_STEPS) * NFEAT + xq * 4;
    uint32_t sx0 = (uint32_t)__cvta_generic_to_shared(sm + OFF_C + xrow * RSTRIDE + xq * 4);
    const uint32_t cbufbytes = ROWS * RSTRIDE * 4;

    __syncthreads();                    // zeroing done before cp.async writes x
    if (xmover) cp16(sx0, xg);          // x_0 -> buffer 0
    cp_commit();

    const float* wq1 = sm + OFF_W1i + (kh * 48) * WROW1 + up * 8 + (up >> 2) * 4;
    const float* wq2a = sm + OFF_W2i + (kh * 32) * WROW2 + up2 * 8 + (up2 >> 2) * 4;        // W2 rows
    const float* wq2b = sm + OFF_W2i + (64 + kh * 16) * WROW2 + up2 * 8 + (up2 >> 2) * 4;   // U2 rows

    for (int t = 0; t < T_STEPS; ++t) {
        cp_wait0();
        __syncthreads();               // barrier 1: x_t + h1(t-1) + h2(t-1) visible
        if (t + 1 < T_STEPS && xmover)
            cp16(sx0 + ((t + 1) & 1) * cbufbytes, xg + (size_t)(t + 1) * NFEAT);
        cp_commit();
        const int rb = t & 1;
        const float* cin  = sm + OFF_C + rb * (ROWS * RSTRIDE);
        float*       cout = sm + OFF_C + (rb ^ 1) * (ROWS * RSTRIDE);

        // ============ phase A: layer 1, all 16 warps ============
        {
            ull acc[4][4];
#pragma unroll
            for (int r = 0; r < 4; r++)
#pragma unroll
                for (int g = 0; g < 4; g++) acc[r][g] = bq1[g];

            // gate cols [x|h1] = cin cols 0..95; this thread: cols kh*48..+47
            panelQ<4, 48, WROW1>(acc, cin + rg * 4 * RSTRIDE + kh * 48, wq1);

#pragma unroll
            for (int r = 0; r < 4; r++)
#pragma unroll
                for (int g = 0; g < 4; g++)
                    acc[r][g] = add2(acc[r][g], __shfl_xor_sync(0xffffffffu, acc[r][g], 16));

            // kh=0 activates rows 0,1 of the tile; kh=1 rows 2,3
#pragma unroll
            for (int r = 0; r < 2; r++) {
                int ar = kh * 2 + r;
                float2 zi = unpack2(acc[ar][0]);
                float2 zf = unpack2(acc[ar][1]);
                float2 zg = unpack2(acc[ar][2]);
                float2 zo = unpack2(acc[ar][3]);
                float i0 = sigm(zi.x), f0 = sigm(zf.x), g0 = tanh_(zg.x), o0 = sigm(zo.x);
                float i1 = sigm(zi.y), f1 = sigm(zf.y), g1 = tanh_(zg.y), o1 = sigm(zo.y);
                c1[r][0] = f0 * c1[r][0] + i0 * g0;
                c1[r][1] = f1 * c1[r][1] + i1 * g1;
                float2 h;
                h.x = o0 * tanh_(c1[r][0]);
                h.y = o1 * tanh_(c1[r][1]);
                int row = rg * 4 + ar;
                *(float2*)(cout + row * RSTRIDE + 32 + 2 * up) = h;   // h1(t)
            }
        }
        __syncthreads();               // barrier 2: h1(t) visible

        // ============ phase B: layer 2, all 16 warps ============
        {
            ull acc2[2][4];
#pragma unroll
            for (int r = 0; r < 2; r++)
#pragma unroll
                for (int g = 0; g < 4; g++) acc2[r][g] = bq2[g];

            // h1(t) lives in cout cols 32..95 ; h2(t-1) in cin cols 96..127
            panelQ<2, 32, WROW2>(acc2, cout + rg2 * 2 * RSTRIDE + 32 + kh * 32, wq2a);
            panelQ<2, 16, WROW2>(acc2, cin  + rg2 * 2 * RSTRIDE + 96 + kh * 16, wq2b);

#pragma unroll
            for (int r = 0; r < 2; r++)
#pragma unroll
                for (int g = 0; g < 4; g++)
                    acc2[r][g] = add2(acc2[r][g], __shfl_xor_sync(0xffffffffu, acc2[r][g], 16));

            // kh=0 activates row 0 of the 2-row tile; kh=1 row 1
            {
                float2 zi = unpack2(acc2[kh][0]);
                float2 zf = unpack2(acc2[kh][1]);
                float2 zg = unpack2(acc2[kh][2]);
                float2 zo = unpack2(acc2[kh][3]);
                float i0 = sigm(zi.x), f0 = sigm(zf.x), g0 = tanh_(zg.x), o0 = sigm(zo.x);
                float i1 = sigm(zi.y), f1 = sigm(zf.y), g1 = tanh_(zg.y), o1 = sigm(zo.y);
                c2[0] = f0 * c2[0] + i0 * g0;
                c2[1] = f1 * c2[1] + i1 * g1;
                float2 h;
                h.x = o0 * tanh_(c2[0]);
                h.y = o1 * tanh_(c2[1]);
                int row = rg2 * 2 + kh;
                *(float2*)(cout + row * RSTRIDE + 96 + 2 * up2) = h;  // h2(t)
            }
        }
        // next iteration's barrier 1 publishes h2(t)
    }
    __syncthreads();

    // final h2 = h2(T-1), written into buf ((T-1)&1)^1, cols 96..127
    const float* h2f = sm + OFF_C + (((T_STEPS - 1) & 1) ^ 1) * (ROWS * RSTRIDE) + 96;

    // ============ head: MHA(seq=1) == identity-attention -> v@Wo, then MLP ============
    float* sv  = sm;            // 32x32 scratch (dead weight region)
    float* so  = sm + 1024;     // 32x32
    float* sd1 = sm + 2048;     // 32x64
    for (int idx = tid; idx < ROWS * 32; idx += THREADS) {
        int r = idx >> 5, j = idx & 31;
        float s = bv[j];
        const float* h2row = h2f + r * RSTRIDE;
#pragma unroll
        for (int d = 0; d < 32; d++) s += h2row[d] * Wv[d * 32 + j];
        sv[idx] = s;
    }
    __syncthreads();
    for (int idx = tid; idx < ROWS * 32; idx += THREADS) {
        int r = idx >> 5, e = idx & 31;
        float s = bo[e];
#pragma unroll
        for (int j = 0; j < 32; j++) s += sv[r * 32 + j] * Wo[j * 32 + e];
        so[idx] = s;
    }
    __syncthreads();
    for (int idx = tid; idx < ROWS * 64; idx += THREADS) {
        int r = idx >> 6, m = idx & 63;
        float s = bd1[m];
#pragma unroll
        for (int e = 0; e < 32; e++) s += so[r * 32 + e] * Wd1[e * 64 + m];
        sd1[idx] = fmaxf(s, 0.0f);
    }
    __syncthreads();
    for (int idx = tid; idx < ROWS * 24; idx += THREADS) {
        int r = idx / 24, p = idx % 24;
        float s = bd2[p];
#pragma unroll
        for (int m = 0; m < 64; m++) s += sd1[r * 64 + m] * Wd2[m * 24 + p];
        out[(size_t)(b0 + r) * 24 + p] = s;
    }
}

extern "C" void kernel_launch(void* const* d_in, const int* in_sizes, int n_in,
                              void* d_out, int out_size) {
    const float* x   = (const float*)d_in[0];
    const float* W1  = (const float*)d_in[1];
    const float* U1w = (const float*)d_in[2];
    const float* b1  = (const float*)d_in[3];
    const float* W2  = (const float*)d_in[4];
    const float* U2w = (const float*)d_in[5];
    const float* b2  = (const float*)d_in[6];
    // d_in[7..10] = Wq, bq, Wk, bk: dead (softmax over seq-len 1 == 1)
    const float* Wv  = (const float*)d_in[11];
    const float* bv  = (const float*)d_in[12];
    const float* Wo  = (const float*)d_in[13];
    const float* bo  = (const float*)d_in[14];
    const float* Wd1 = (const float*)d_in[15];
    const float* bd1 = (const float*)d_in[16];
    const float* Wd2 = (const float*)d_in[17];
    const float* bd2 = (const float*)d_in[18];

    size_t smem = SMEM_FLOATS * sizeof(float);   // 198656 B
    cudaFuncSetAttribute(lstm_fused_kernel,
                         cudaFuncAttributeMaxDynamicSharedMemorySize, (int)smem);
    lstm_fused_kernel<<<CTAS, THREADS, smem>>>(
        x, W1, U1w, b1, W2, U2w, b2, Wv, bv, Wo, bo, Wd1, bd1, Wd2, bd2,
        (float*)d_out);
}

// round 8
// speedup vs baseline: 1.0887x; 1.0887x over previous
#include <cuda_runtime.h>
#include <cstdint>

#define T_STEPS 336
#define BATCH   4096
#define NFEAT   32
#define UN1     64
#define UN2     32
#define G1      256   // 4*UN1
#define G2      128   // 4*UN2
#define ROWS    32
#define THREADS 512
#define CTAS    (BATCH / ROWS)   // 128
#define RSTRIDE 128   // combined row: [x(32)|h1(64)|h2(32)]

// ---- shared memory layout (float offsets) ----
#define OFF_W1  0                              // stacked [W1;U1]: 96 x 256
#define OFF_W2  (OFF_W1 + 96 * G1)             // 24576: stacked [W2;U2]: 96 x 128
#define OFF_C   (OFF_W2 + 96 * G2)             // 36864: 2 buffers x 32 x 128
#define SMEM_FLOATS (OFF_C + 2 * ROWS * RSTRIDE) // 45056 -> 180224 bytes

typedef unsigned long long ull;

// ---------------- packed f32x2 helpers ----------------
__device__ __forceinline__ ull pack2(float a) {
    ull r; asm("mov.b64 %0, {%1, %1};" : "=l"(r) : "f"(a)); return r;
}
__device__ __forceinline__ ull pakf2(float x, float y) {
    ull r; asm("mov.b64 %0, {%1, %2};" : "=l"(r) : "f"(x), "f"(y)); return r;
}
__device__ __forceinline__ ull fma2(ull a, ull b, ull c) {
    ull d; asm("fma.rn.f32x2 %0, %1, %2, %3;" : "=l"(d) : "l"(a), "l"(b), "l"(c)); return d;
}
__device__ __forceinline__ ull add2(ull a, ull b) {
    ull d; asm("add.rn.f32x2 %0, %1, %2;" : "=l"(d) : "l"(a), "l"(b)); return d;
}
__device__ __forceinline__ float2 unpack2(ull v) {
    float2 r; asm("mov.b64 {%0, %1}, %2;" : "=f"(r.x), "=f"(r.y) : "l"(v)); return r;
}

// ---------------- activations (fast HW exp/rcp, ~1e-6 err) ----------------
__device__ __forceinline__ float sigm(float x) {
    float e = __expf(-x);
    return __fdividef(1.0f, 1.0f + e);
}
__device__ __forceinline__ float tanh_(float x) {
    float ax = fabsf(x);
    float e  = __expf(-2.0f * ax);
    float r  = __fdividef(1.0f - e, 1.0f + e);
    return copysignf(r, x);
}

// ---------------- cp.async helpers ----------------
__device__ __forceinline__ void cp16(uint32_t saddr, const float* g) {
    asm volatile("cp.async.cg.shared.global [%0], [%1], 16;" :: "r"(saddr), "l"(g));
}
__device__ __forceinline__ void cp_commit() { asm volatile("cp.async.commit_group;"); }
__device__ __forceinline__ void cp_wait0()  { asm volatile("cp.async.wait_group 0;" ::: "memory"); }

// 48-column panel: R rows x (2 units x 4 gates). Flat weight layout (R5-proven):
// weights at wb + k*WS + g*GS; input float4 loads (broadcast within half-warp).
template <int R, int WS, int GS>
__device__ __forceinline__ void panel48(ull (&acc)[R][4],
                                        const float* __restrict__ in,
                                        const float* __restrict__ wb) {
#pragma unroll 2
    for (int k = 0; k < 48; k += 4) {
        float4 a[R];
#pragma unroll
        for (int r = 0; r < R; r++) a[r] = *(const float4*)(in + r * RSTRIDE + k);
#pragma unroll
        for (int kk = 0; kk < 4; kk++) {
            const float* w = wb + (k + kk) * WS;
            ull w0 = *(const ull*)(w);
            ull w1 = *(const ull*)(w + GS);
            ull w2 = *(const ull*)(w + 2 * GS);
            ull w3 = *(const ull*)(w + 3 * GS);
#pragma unroll
            for (int r = 0; r < R; r++) {
                float av = (kk == 0) ? a[r].x : (kk == 1) ? a[r].y : (kk == 2) ? a[r].z : a[r].w;
                ull p = pack2(av);
                acc[r][0] = fma2(p, w0, acc[r][0]);
                acc[r][1] = fma2(p, w1, acc[r][1]);
                acc[r][2] = fma2(p, w2, acc[r][2]);
                acc[r][3] = fma2(p, w3, acc[r][3]);
            }
        }
    }
}

__global__ void __launch_bounds__(THREADS, 1)
lstm_fused_kernel(const float* __restrict__ x,
                  const float* __restrict__ W1, const float* __restrict__ U1w, const float* __restrict__ b1,
                  const float* __restrict__ W2, const float* __restrict__ U2w, const float* __restrict__ b2,
                  const float* __restrict__ Wv, const float* __restrict__ bv,
                  const float* __restrict__ Wo, const float* __restrict__ bo,
                  const float* __restrict__ Wd1, const float* __restrict__ bd1,
                  const float* __restrict__ Wd2, const float* __restrict__ bd2,
                  float* __restrict__ out) {
    extern __shared__ float sm[];
    const int tid = threadIdx.x;
    const int b0  = blockIdx.x * ROWS;

    // ---- stage stacked weights into SMEM (one time, R5 layout) ----
    for (int i = tid; i < (NFEAT * G1) / 4; i += THREADS)
        ((float4*)(sm + OFF_W1))[i] = ((const float4*)W1)[i];
    for (int i = tid; i < (UN1 * G1) / 4; i += THREADS)
        ((float4*)(sm + OFF_W1 + NFEAT * G1))[i] = ((const float4*)U1w)[i];
    for (int i = tid; i < (UN1 * G2) / 4; i += THREADS)
        ((float4*)(sm + OFF_W2))[i] = ((const float4*)W2)[i];
    for (int i = tid; i < (UN2 * G2) / 4; i += THREADS)
        ((float4*)(sm + OFF_W2 + UN1 * G2))[i] = ((const float4*)U2w)[i];
    for (int i = tid; i < 2 * ROWS * RSTRIDE; i += THREADS) sm[OFF_C + i] = 0.0f;

    // ---- thread mapping: EVERY thread owns an L1 slice AND an L2 slice ----
    const int wg = tid >> 5;           // 0..15
    const int l  = tid & 31;
    const int kh = l >> 4;             // K-half (0/1)
    // L1: 8 row groups (4 rows each) x 32 unit pairs x 2 kh = 512
    const int rg = wg & 7;
    const int up = (l & 15) | ((wg >> 3) << 4);
    // L2: 16 row groups (2 rows each) x 16 unit pairs x 2 kh = 512
    const int rg2 = wg;
    const int up2 = l & 15;

    // bias -> registers (kh==0 half carries it; partner contributes 0)
    ull bq1[4], bq2[4];
#pragma unroll
    for (int g = 0; g < 4; g++) {
        float2 v1 = (kh == 0) ? *(const float2*)(b1 + g * UN1 + 2 * up)  : make_float2(0.f, 0.f);
        float2 v2 = (kh == 0) ? *(const float2*)(b2 + g * UN2 + 2 * up2) : make_float2(0.f, 0.f);
        bq1[g] = pakf2(v1.x, v1.y);
        bq2[g] = pakf2(v2.x, v2.y);
    }

    // per-thread cell state: L1 2 rows x 2 units, L2 1 row x 2 units
    float c1[2][2], c2[2];
    c1[0][0] = c1[0][1] = c1[1][0] = c1[1][1] = 0.0f;
    c2[0] = c2[1] = 0.0f;

    // ---- x prefetch: threads 0-255 move one float4 per step ----
    const bool xmover = (tid < 256);
    const int xrow = tid >> 3;
    const int xq   = tid & 7;
    const float* xg = x + ((size_t)(b0 + xrow) * T_STEPS) * NFEAT + xq * 4;
    uint32_t sx0 = (uint32_t)__cvta_generic_to_shared(sm + OFF_C + xrow * RSTRIDE + xq * 4);
    const uint32_t cbufbytes = ROWS * RSTRIDE * 4;

    __syncthreads();                    // zeroing visible before cp.async writes x
    if (xmover) cp16(sx0, xg);          // x_0 -> buffer 0
    cp_commit();

    const float* wb1 = sm + OFF_W1 + (kh * 48) * G1 + 2 * up;    // L1 weights, this K-half
    const float* wb2 = sm + OFF_W2 + (kh * 48) * G2 + 2 * up2;   // L2 weights, this K-half

    // Iter t: L1 computes step t (t<T), L2 computes step t-1 (t>=1).
    // Both read buf rb = t&1, both write buf wb. One barrier per step.
    for (int t = 0; t <= T_STEPS; ++t) {
        if (t < T_STEPS) cp_wait0();
        __syncthreads();
        if (t + 1 < T_STEPS && xmover)
            cp16(sx0 + ((t + 1) & 1) * cbufbytes, xg + (size_t)(t + 1) * NFEAT);
        cp_commit();
        const int rb = t & 1;
        const float* cin  = sm + OFF_C + rb * (ROWS * RSTRIDE);
        float*       cout = sm + OFF_C + (rb ^ 1) * (ROWS * RSTRIDE);

        // ---------- L1 slice: step t ----------
        if (t < T_STEPS) {
            ull acc[4][4];
#pragma unroll
            for (int r = 0; r < 4; r++)
#pragma unroll
                for (int g = 0; g < 4; g++) acc[r][g] = bq1[g];

            // gate K-rows = [x|h1] = cin cols 0..95; this thread: cols kh*48..+47
            panel48<4, G1, UN1>(acc, cin + rg * 4 * RSTRIDE + kh * 48, wb1);

#pragma unroll
            for (int r = 0; r < 4; r++)
#pragma unroll
                for (int g = 0; g < 4; g++)
                    acc[r][g] = add2(acc[r][g], __shfl_xor_sync(0xffffffffu, acc[r][g], 16));

            // kh=0 activates tile rows 0,1; kh=1 rows 2,3 (Keras gates i,f,c,o)
#pragma unroll
            for (int r = 0; r < 2; r++) {
                int ar = kh * 2 + r;
                float2 zi = unpack2(acc[ar][0]);
                float2 zf = unpack2(acc[ar][1]);
                float2 zg = unpack2(acc[ar][2]);
                float2 zo = unpack2(acc[ar][3]);
                float i0 = sigm(zi.x), f0 = sigm(zf.x), g0 = tanh_(zg.x), o0 = sigm(zo.x);
                float i1 = sigm(zi.y), f1 = sigm(zf.y), g1 = tanh_(zg.y), o1 = sigm(zo.y);
                c1[r][0] = f0 * c1[r][0] + i0 * g0;
                c1[r][1] = f1 * c1[r][1] + i1 * g1;
                float2 h;
                h.x = o0 * tanh_(c1[r][0]);
                h.y = o1 * tanh_(c1[r][1]);
                *(float2*)(cout + (rg * 4 + ar) * RSTRIDE + 32 + 2 * up) = h;   // h1(t)
            }
        }

        // ---------- L2 slice: step t-1 ----------
        if (t >= 1) {
            ull acc2[2][4];
#pragma unroll
            for (int r = 0; r < 2; r++)
#pragma unroll
                for (int g = 0; g < 4; g++) acc2[r][g] = bq2[g];

            // gate K-rows = [h1(t-1)|h2(t-2)] = cin cols 32..127; this thread: 32+kh*48..+47
            panel48<2, G2, UN2>(acc2, cin + rg2 * 2 * RSTRIDE + 32 + kh * 48, wb2);

#pragma unroll
            for (int r = 0; r < 2; r++)
#pragma unroll
                for (int g = 0; g < 4; g++)
                    acc2[r][g] = add2(acc2[r][g], __shfl_xor_sync(0xffffffffu, acc2[r][g], 16));

            // kh selects which of the 2 tile rows this thread activates
            {
                float2 zi = unpack2(acc2[kh][0]);
                float2 zf = unpack2(acc2[kh][1]);
                float2 zg = unpack2(acc2[kh][2]);
                float2 zo = unpack2(acc2[kh][3]);
                float i0 = sigm(zi.x), f0 = sigm(zf.x), g0 = tanh_(zg.x), o0 = sigm(zo.x);
                float i1 = sigm(zi.y), f1 = sigm(zf.y), g1 = tanh_(zg.y), o1 = sigm(zo.y);
                c2[0] = f0 * c2[0] + i0 * g0;
                c2[1] = f1 * c2[1] + i1 * g1;
                float2 h;
                h.x = o0 * tanh_(c2[0]);
                h.y = o1 * tanh_(c2[1]);
                *(float2*)(cout + (rg2 * 2 + kh) * RSTRIDE + 96 + 2 * up2) = h; // h2(t-1)
            }
        }
    }
    __syncthreads();

    // final h2 = h2(T-1), written at iter t=T into buf ((T&1)^1)
    const float* h2f = sm + OFF_C + ((T_STEPS & 1) ^ 1) * (ROWS * RSTRIDE) + 96;

    // ============ head: MHA(seq=1) == identity-attention -> v@Wo, then MLP ============
    float* sv  = sm;            // scratch in dead weight region
    float* so  = sm + 1024;
    float* sd1 = sm + 2048;
    for (int idx = tid; idx < ROWS * 32; idx += THREADS) {
        int r = idx >> 5, j = idx & 31;
        float s = bv[j];
        const float* h2row = h2f + r * RSTRIDE;
#pragma unroll
        for (int d = 0; d < 32; d++) s += h2row[d] * Wv[d * 32 + j];
        sv[idx] = s;
    }
    __syncthreads();
    for (int idx = tid; idx < ROWS * 32; idx += THREADS) {
        int r = idx >> 5, e = idx & 31;
        float s = bo[e];
#pragma unroll
        for (int j = 0; j < 32; j++) s += sv[r * 32 + j] * Wo[j * 32 + e];
        so[idx] = s;
    }
    __syncthreads();
    for (int idx = tid; idx < ROWS * 64; idx += THREADS) {
        int r = idx >> 6, m = idx & 63;
        float s = bd1[m];
#pragma unroll
        for (int e = 0; e < 32; e++) s += so[r * 32 + e] * Wd1[e * 64 + m];
        sd1[idx] = fmaxf(s, 0.0f);
    }
    __syncthreads();
    for (int idx = tid; idx < ROWS * 24; idx += THREADS) {
        int r = idx / 24, p = idx % 24;
        float s = bd2[p];
#pragma unroll
        for (int m = 0; m < 64; m++) s += sd1[r * 64 + m] * Wd2[m * 24 + p];
        out[(size_t)(b0 + r) * 24 + p] = s;
    }
}

extern "C" void kernel_launch(void* const* d_in, const int* in_sizes, int n_in,
                              void* d_out, int out_size) {
    const float* x   = (const float*)d_in[0];
    const float* W1  = (const float*)d_in[1];
    const float* U1w = (const float*)d_in[2];
    const float* b1  = (const float*)d_in[3];
    const float* W2  = (const float*)d_in[4];
    const float* U2w = (const float*)d_in[5];
    const float* b2  = (const float*)d_in[6];
    // d_in[7..10] = Wq, bq, Wk, bk: dead (softmax over seq-len 1 == 1)
    const float* Wv  = (const float*)d_in[11];
    const float* bv  = (const float*)d_in[12];
    const float* Wo  = (const float*)d_in[13];
    const float* bo  = (const float*)d_in[14];
    const float* Wd1 = (const float*)d_in[15];
    const float* bd1 = (const float*)d_in[16];
    const float* Wd2 = (const float*)d_in[17];
    const float* bd2 = (const float*)d_in[18];

    size_t smem = SMEM_FLOATS * sizeof(float);   // 180224 B
    cudaFuncSetAttribute(lstm_fused_kernel,
                         cudaFuncAttributeMaxDynamicSharedMemorySize, (int)smem);
    lstm_fused_kernel<<<CTAS, THREADS, smem>>>(
        x, W1, U1w, b1, W2, U2w, b2, Wv, bv, Wo, bo, Wd1, bd1, Wd2, bd2,
        (float*)d_out);
}